// round 12
// baseline (speedup 1.0000x reference)
#include <cuda_runtime.h>
#include <cstdint>

// Problem constants (from reference setup_inputs)
#define BB 16
#define TT 4096
#define DD 768
#define SS 64
#define D4 (DD / 4)          // 192 float4 lanes per row
#define OUT_VEC ((size_t)BB * 2 * SS * DD)   // 1,572,864 floats

#define CHUNK 8                          // tokens per bulk-copy chunk (24 KB)
#define STAGE_FLOATS (CHUNK * DD)        // 6144 floats = 24576 bytes
#define NSTAGE 2
#define NTHREADS 384                     // two 192-lane halves

__device__ __forceinline__ uint32_t smem_u32(const void* p) {
    uint32_t a;
    asm("{ .reg .u64 t; cvta.to.shared.u64 t, %1; cvt.u32.u64 %0, t; }"
        : "=r"(a) : "l"(p));
    return a;
}

__device__ __forceinline__ void mbar_wait(uint32_t mbar, uint32_t parity) {
    uint32_t done;
    asm volatile(
        "{\n\t.reg .pred p;\n\t"
        "mbarrier.try_wait.parity.acquire.cta.shared::cta.b64 p, [%1], %2;\n\t"
        "selp.b32 %0, 1, 0, p;\n\t}"
        : "=r"(done) : "r"(mbar), "r"(parity) : "memory");
    while (!done) {
        asm volatile(
            "{\n\t.reg .pred p;\n\t"
            "mbarrier.try_wait.parity.acquire.cta.shared::cta.b64 p, [%1], %2, 0x989680;\n\t"
            "selp.b32 %0, 1, 0, p;\n\t}"
            : "=r"(done) : "r"(mbar), "r"(parity) : "memory");
    }
}

// One block per PAIR of adjacent segments (always contiguous in token space).
// Half 0 (warps 0-5, lanes 0-191) owns segment 2u; half 1 (warps 6-11) owns
// segment 2u+1. One 2-stage cp.async.bulk stream covers the merged span in
// 24 KB chunks; each thread accumulates only rows inside its half's range.
// Amortizes prologue/fill-bubble over 2x work; 4 CTAs/SM = 48 warps resident.
__global__ __launch_bounds__(NTHREADS, 4) void pooling_kernel(
    const float* __restrict__ wv,           // [B, T, D]
    const int* __restrict__ rep_ids,        // [B, S]
    const int* __restrict__ rep_mask,       // [B, S] bool marshaled as int32
    const int* __restrict__ lens,           // [B, S]
    const int* __restrict__ len_mask,       // [B, S] bool marshaled as int32
    float* __restrict__ out,                // [B, 2S, D] (+ optional [B, 2S] mask tail)
    int write_mask_tail)
{
    __shared__ __align__(128) float buf[NSTAGE][STAGE_FLOATS];
    __shared__ __align__(8) unsigned long long mbar[NSTAGE];
    __shared__ int sh_bounds[3];            // start0, mid (=end0=start1), end1
    __shared__ float sh_warp[12];

    const int q = blockIdx.x;               // 0 .. BB*SS/2 - 1
    const int b = q / (SS / 2);
    const int u = q % (SS / 2);
    const int tid = threadIdx.x;            // 0..383
    const int half = tid / 192;             // 0 or 1
    const int lane192 = tid % 192;          // lane within half (owns float4 col)
    const int lane = tid & 31;
    const int wid = tid >> 5;               // 0..11
    const int s = 2 * u + half;             // this half's segment id

    if (tid == 0) {
        const int* lrow = lens + b * SS;
        const int s0 = 2 * u;
        int c0 = 0;                          // cum up to s0-1
        #pragma unroll 8
        for (int i = 0; i < SS; i++) {
            int li = lrow[i];
            if (i < s0) c0 += li;
        }
        long long c1 = (long long)c0 + (long long)lrow[s0];          // cum[s0]
        long long c2 = c1 + (long long)lrow[s0 + 1];                 // cum[s0+1]
        int start0 = c0 < 0 ? 0 : (c0 > TT ? TT : c0);
        int mid    = c1 < 0 ? 0 : (c1 > TT ? TT : (int)c1);
        int end1   = c2 < 0 ? 0 : (c2 > TT ? TT : (int)c2);
        if (mid < start0) mid = start0;
        if (end1 < mid) end1 = mid;
        sh_bounds[0] = start0;
        sh_bounds[1] = mid;
        sh_bounds[2] = end1;
        uint32_t b0 = smem_u32(&mbar[0]);
        uint32_t b1 = smem_u32(&mbar[1]);
        asm volatile("mbarrier.init.shared.b64 [%0], 1;" :: "r"(b0) : "memory");
        asm volatile("mbarrier.init.shared.b64 [%0], 1;" :: "r"(b1) : "memory");
        asm volatile("fence.proxy.async.shared::cta;" ::: "memory");
    }
    __syncthreads();
    const int start0 = sh_bounds[0];
    const int mid    = sh_bounds[1];
    const int end1   = sh_bounds[2];
    const int total  = end1 - start0;
    const int nchunks = (total + CHUNK - 1) / CHUNK;
    // This half's token range:
    const int myStart = half ? mid : start0;
    const int myEnd   = half ? end1 : mid;

    const float4* base = reinterpret_cast<const float4*>(wv + (size_t)b * TT * DD);
    const char* src_base = reinterpret_cast<const char*>(wv + (size_t)b * TT * DD
                                                            + (size_t)start0 * DD);

    auto issue = [&](int i) {
        int t0 = i * CHUNK;
        int rows = total - t0;
        if (rows > CHUNK) rows = CHUNK;
        uint32_t bytes = (uint32_t)rows * DD * 4u;
        uint32_t dst = smem_u32(&buf[i & 1][0]);
        uint32_t bar = smem_u32(&mbar[i & 1]);
        asm volatile("mbarrier.arrive.expect_tx.shared.b64 _, [%0], %1;"
                     :: "r"(bar), "r"(bytes) : "memory");
        asm volatile(
            "cp.async.bulk.shared::cluster.global.mbarrier::complete_tx::bytes "
            "[%0], [%1], %2, [%3];"
            :: "r"(dst), "l"(src_base + (size_t)t0 * DD * 4), "r"(bytes), "r"(bar)
            : "memory");
    };
    if (tid == 0) {
        if (nchunks > 0) issue(0);
        if (nchunks > 1) issue(1);
    }

    // Rep gather (per half) overlaps with pipeline fill.
    int rid = rep_ids[b * SS + s];
    if (rid < 0) rid = 0;
    if (rid >= TT) rid = TT - 1;
    float4 r = __ldg(base + (size_t)rid * D4 + lane192);
    const float lm = (len_mask[b * SS + s] != 0) ? 1.f : 0.f;
    const float rm = (rep_mask[b * SS + s] != 0) ? 1.f : 0.f;

    float sx = 0.f, sy = 0.f, sz = 0.f, sw = 0.f;
    float cx = 0.f, cy = 0.f, cz = 0.f, cw = 0.f;

    for (int i = 0; i < nchunks; i++) {
        const int stage = i & 1;
        const uint32_t parity = (uint32_t)((i >> 1) & 1);
        mbar_wait(smem_u32(&mbar[stage]), parity);

        const int tbase = start0 + i * CHUNK;   // global token of row 0
        const float4* bp = reinterpret_cast<const float4*>(&buf[stage][0]);
        #pragma unroll
        for (int rr = 0; rr < CHUNK; rr++) {
            int tg = tbase + rr;
            if (tg >= myStart && tg < myEnd) {
                float4 v = bp[rr * D4 + lane192];
                sx += v.x; sy += v.y; sz += v.z; sw += v.w;
                cx += (v.x != 0.f) ? 1.f : 0.f;
                cy += (v.y != 0.f) ? 1.f : 0.f;
                cz += (v.z != 0.f) ? 1.f : 0.f;
                cw += (v.w != 0.f) ? 1.f : 0.f;
            }
        }
        __syncthreads();   // all warps done reading this stage
        if (tid == 0 && i + 2 < nchunks) issue(i + 2);
    }

    // Per-segment emptiness check (seg_cnt.sum(-1) == 0), per half.
    float tot = cx + cy + cz + cw;
    #pragma unroll
    for (int off = 16; off > 0; off >>= 1)
        tot += __shfl_xor_sync(0xffffffffu, tot, off);
    if (lane == 0) sh_warp[wid] = tot;
    __syncthreads();
    const int wb = half * 6;
    float half_tot = sh_warp[wb] + sh_warp[wb + 1] + sh_warp[wb + 2]
                   + sh_warp[wb + 3] + sh_warp[wb + 4] + sh_warp[wb + 5];
    const bool empty = (half_tot == 0.f);

    float4 o;
    if (empty) {
        // fallback to word_vectors[0, 0, :]
        float4 w0 = __ldg(reinterpret_cast<const float4*>(wv) + lane192);
        o.x = w0.x * lm; o.y = w0.y * lm; o.z = w0.z * lm; o.w = w0.w * lm;
    } else {
        float dx = (cx == 0.f) ? 1.f : cx;
        float dy = (cy == 0.f) ? 1.f : cy;
        float dz = (cz == 0.f) ? 1.f : cz;
        float dw = (cw == 0.f) ? 1.f : cw;
        o.x = (sx / dx) * lm;
        o.y = (sy / dy) * lm;
        o.z = (sz / dz) * lm;
        o.w = (sw / dw) * lm;
    }
    float4* out4 = reinterpret_cast<float4*>(out);
    // mean_vec -> out[b, S + s, :]
    __stcs(&out4[((size_t)b * 2 * SS + SS + s) * D4 + lane192], o);
    // rep_vec -> out[b, s, :]
    r.x *= rm; r.y *= rm; r.z *= rm; r.w *= rm;
    __stcs(&out4[((size_t)b * 2 * SS + s) * D4 + lane192], r);

    // output mask tail (flattened tuple): out_tail[b, c] with c in [0, 2S)
    if (write_mask_tail) {
        float* out_tail = out + OUT_VEC;
        if (lane192 == 0) out_tail[b * 2 * SS + s]      = rm;   // rep mask half
        if (lane192 == 1) out_tail[b * 2 * SS + SS + s] = lm;   // len mask half
    }
}

extern "C" void kernel_launch(void* const* d_in, const int* in_sizes, int n_in,
                              void* d_out, int out_size)
{
    const float* wv       = (const float*)d_in[0];
    const int*   rep_ids  = (const int*)d_in[1];
    const int*   rep_mask = (const int*)d_in[2];
    const int*   lens     = (const int*)d_in[3];
    const int*   len_mask = (const int*)d_in[4];
    float* out = (float*)d_out;

    int write_mask_tail = ((size_t)out_size > OUT_VEC) ? 1 : 0;
    pooling_kernel<<<BB * SS / 2, NTHREADS>>>(wv, rep_ids, rep_mask, lens, len_mask,
                                              out, write_mask_tail);
}

// round 13
// speedup vs baseline: 1.0057x; 1.0057x over previous
#include <cuda_runtime.h>
#include <cstdint>

// Problem constants (from reference setup_inputs)
#define BB 16
#define TT 4096
#define DD 768
#define SS 64
#define D4 (DD / 4)          // 192 float4 lanes per row
#define OUT_VEC ((size_t)BB * 2 * SS * DD)   // 1,572,864 floats

// One block per (b, s) segment. 192 threads; thread tid owns float4 column tid.
// Token loop batched x4 (divides L=64; 4 independent LDG.128.CS in flight).
// Best timed configuration across 12 measured variants (LDG beats TMA on the
// graph-replay timed metric despite TMA's better isolated ncu kernel time).
__global__ __launch_bounds__(192, 7) void pooling_kernel(
    const float* __restrict__ wv,           // [B, T, D]
    const int* __restrict__ rep_ids,        // [B, S]
    const int* __restrict__ rep_mask,       // [B, S] bool marshaled as int32
    const int* __restrict__ lens,           // [B, S]
    const int* __restrict__ len_mask,       // [B, S] bool marshaled as int32
    float* __restrict__ out,                // [B, 2S, D] (+ optional [B, 2S] mask tail)
    int write_mask_tail)
{
    const int blk = blockIdx.x;             // b*S + s
    const int b = blk / SS;
    const int s = blk % SS;
    const int tid = threadIdx.x;            // 0..191

    __shared__ int sh_bounds[2];
    __shared__ float sh_cnt[192];
    __shared__ int sh_empty;

    if (tid == 0) {
        const int* lrow = lens + b * SS;
        int start = 0;
        #pragma unroll 8
        for (int i = 0; i < SS; i++) {
            int li = lrow[i];
            if (i < s) start += li;
        }
        long long endl = (long long)start + (long long)lrow[s];
        if (start < 0) start = 0;
        if (start > TT) start = TT;
        int end = (endl > TT) ? TT : (int)endl;
        if (end < start) end = start;
        sh_bounds[0] = start;
        sh_bounds[1] = end;
    }
    __syncthreads();
    const int start = sh_bounds[0];
    const int end   = sh_bounds[1];

    // Masks early (tiny loads overlap the stream).
    const float lm = (len_mask[b * SS + s] != 0) ? 1.f : 0.f;
    const float rm = (rep_mask[b * SS + s] != 0) ? 1.f : 0.f;

    const float4* base = reinterpret_cast<const float4*>(wv + (size_t)b * TT * DD);
    const float4* p = base + (size_t)start * D4 + tid;

    float sx = 0.f, sy = 0.f, sz = 0.f, sw = 0.f;
    float cx = 0.f, cy = 0.f, cz = 0.f, cw = 0.f;

    int t = start;
    // Main loop: 4 tokens per iteration, 4 independent LDG.128.CS in flight.
    for (; t + 4 <= end; t += 4, p += 4 * D4) {
        float4 v0 = __ldcs(p);
        float4 v1 = __ldcs(p + D4);
        float4 v2 = __ldcs(p + 2 * D4);
        float4 v3 = __ldcs(p + 3 * D4);

        sx += v0.x + v1.x + v2.x + v3.x;
        sy += v0.y + v1.y + v2.y + v3.y;
        sz += v0.z + v1.z + v2.z + v3.z;
        sw += v0.w + v1.w + v2.w + v3.w;

        cx += ((v0.x != 0.f) ? 1.f : 0.f) + ((v1.x != 0.f) ? 1.f : 0.f)
            + ((v2.x != 0.f) ? 1.f : 0.f) + ((v3.x != 0.f) ? 1.f : 0.f);
        cy += ((v0.y != 0.f) ? 1.f : 0.f) + ((v1.y != 0.f) ? 1.f : 0.f)
            + ((v2.y != 0.f) ? 1.f : 0.f) + ((v3.y != 0.f) ? 1.f : 0.f);
        cz += ((v0.z != 0.f) ? 1.f : 0.f) + ((v1.z != 0.f) ? 1.f : 0.f)
            + ((v2.z != 0.f) ? 1.f : 0.f) + ((v3.z != 0.f) ? 1.f : 0.f);
        cw += ((v0.w != 0.f) ? 1.f : 0.f) + ((v1.w != 0.f) ? 1.f : 0.f)
            + ((v2.w != 0.f) ? 1.f : 0.f) + ((v3.w != 0.f) ? 1.f : 0.f);
    }
    // Tail (general correctness for lengths % 4 != 0)
    for (; t < end; t++, p += D4) {
        float4 v = __ldcs(p);
        sx += v.x; sy += v.y; sz += v.z; sw += v.w;
        cx += (v.x != 0.f) ? 1.f : 0.f;
        cy += (v.y != 0.f) ? 1.f : 0.f;
        cz += (v.z != 0.f) ? 1.f : 0.f;
        cw += (v.w != 0.f) ? 1.f : 0.f;
    }

    // Whole-segment emptiness check (seg_cnt.sum(-1) == 0)
    sh_cnt[tid] = cx + cy + cz + cw;
    __syncthreads();
    if (tid == 0) {
        float tot = 0.f;
        #pragma unroll 8
        for (int i = 0; i < 192; i++) tot += sh_cnt[i];
        sh_empty = (tot == 0.f) ? 1 : 0;
    }
    __syncthreads();
    const bool empty = (sh_empty != 0);

    float4 o;
    if (empty) {
        // fallback to word_vectors[0, 0, :]
        float4 w0 = __ldg(reinterpret_cast<const float4*>(wv) + tid);
        o.x = w0.x * lm; o.y = w0.y * lm; o.z = w0.z * lm; o.w = w0.w * lm;
    } else {
        float dx = (cx == 0.f) ? 1.f : cx;
        float dy = (cy == 0.f) ? 1.f : cy;
        float dz = (cz == 0.f) ? 1.f : cz;
        float dw = (cw == 0.f) ? 1.f : cw;
        o.x = (sx / dx) * lm;
        o.y = (sy / dy) * lm;
        o.z = (sz / dz) * lm;
        o.w = (sw / dw) * lm;
    }
    // mean_vec -> out[b, S + s, :]  (write-once -> streaming store)
    float4* out4 = reinterpret_cast<float4*>(out);
    __stcs(&out4[((size_t)b * 2 * SS + SS + s) * D4 + tid], o);

    // rep_vec: gather word_vectors[b, rep_ids[b,s], :] * rep_mask
    // (L2 hit: the rep row lies inside this block's just-streamed span)
    int rid = rep_ids[b * SS + s];
    if (rid < 0) rid = 0;
    if (rid >= TT) rid = TT - 1;
    float4 r = __ldg(base + (size_t)rid * D4 + tid);
    r.x *= rm; r.y *= rm; r.z *= rm; r.w *= rm;
    __stcs(&out4[((size_t)b * 2 * SS + s) * D4 + tid], r);

    // output mask tail (flattened tuple): out_tail[b, c] with c in [0, 2S)
    if (write_mask_tail) {
        float* out_tail = out + OUT_VEC;
        if (tid == 0) out_tail[b * 2 * SS + s]      = rm;   // rep mask half
        if (tid == 1) out_tail[b * 2 * SS + SS + s] = lm;   // len mask half
    }
}

extern "C" void kernel_launch(void* const* d_in, const int* in_sizes, int n_in,
                              void* d_out, int out_size)
{
    const float* wv       = (const float*)d_in[0];
    const int*   rep_ids  = (const int*)d_in[1];
    const int*   rep_mask = (const int*)d_in[2];
    const int*   lens     = (const int*)d_in[3];
    const int*   len_mask = (const int*)d_in[4];
    float* out = (float*)d_out;

    int write_mask_tail = ((size_t)out_size > OUT_VEC) ? 1 : 0;
    pooling_kernel<<<BB * SS, 192>>>(wv, rep_ids, rep_mask, lens, len_mask, out,
                                     write_mask_tail);
}

// round 14
// speedup vs baseline: 1.0626x; 1.0566x over previous
#include <cuda_runtime.h>
#include <cstdint>

// Problem constants (from reference setup_inputs)
#define BB 16
#define TT 4096
#define DD 768
#define SS 64
#define D4 (DD / 4)          // 192 float4 lanes per row
#define OUT_VEC ((size_t)BB * 2 * SS * DD)   // 1,572,864 floats

#define CHUNK 4                          // tokens per bulk-copy chunk
#define STAGE_FLOATS (CHUNK * DD)        // 3072 floats = 12288 bytes
#define NSTAGE 2

__device__ __forceinline__ uint32_t smem_u32(const void* p) {
    uint32_t a;
    asm("{ .reg .u64 t; cvta.to.shared.u64 t, %1; cvt.u32.u64 %0, t; }"
        : "=r"(a) : "l"(p));
    return a;
}

__device__ __forceinline__ void mbar_wait(uint32_t mbar, uint32_t parity) {
    uint32_t done;
    asm volatile(
        "{\n\t.reg .pred p;\n\t"
        "mbarrier.try_wait.parity.acquire.cta.shared::cta.b64 p, [%1], %2;\n\t"
        "selp.b32 %0, 1, 0, p;\n\t}"
        : "=r"(done) : "r"(mbar), "r"(parity) : "memory");
    while (!done) {
        asm volatile(
            "{\n\t.reg .pred p;\n\t"
            "mbarrier.try_wait.parity.acquire.cta.shared::cta.b64 p, [%1], %2, 0x989680;\n\t"
            "selp.b32 %0, 1, 0, p;\n\t}"
            : "=r"(done) : "r"(mbar), "r"(parity) : "memory");
    }
}

// One block per (b, s) segment. 2-stage cp.async.bulk pipeline streams the
// segment's token rows into smem (12 KB chunks); 192 threads reduce from smem.
// Outstanding HBM bytes come from the bulk-copy engine, not warp LDG slots.
// Best measured configuration (ncu kernel 35.9us, DRAM 72.3%).
__global__ __launch_bounds__(192, 8) void pooling_kernel(
    const float* __restrict__ wv,           // [B, T, D]
    const int* __restrict__ rep_ids,        // [B, S]
    const int* __restrict__ rep_mask,       // [B, S] bool marshaled as int32
    const int* __restrict__ lens,           // [B, S]
    const int* __restrict__ len_mask,       // [B, S] bool marshaled as int32
    float* __restrict__ out,                // [B, 2S, D] (+ optional [B, 2S] mask tail)
    int write_mask_tail)
{
    __shared__ __align__(128) float buf[NSTAGE][STAGE_FLOATS];
    __shared__ __align__(8) unsigned long long mbar[NSTAGE];
    __shared__ int sh_bounds[2];
    __shared__ float sh_warp[6];

    const int blk = blockIdx.x;             // b*S + s
    const int b = blk / SS;
    const int s = blk % SS;
    const int tid = threadIdx.x;            // 0..191
    const int lane = tid & 31;
    const int wid = tid >> 5;

    if (tid == 0) {
        const int* lrow = lens + b * SS;
        int start = 0;
        #pragma unroll 8
        for (int i = 0; i < SS; i++) {
            int li = lrow[i];
            if (i < s) start += li;
        }
        long long endl = (long long)start + (long long)lrow[s];
        if (start < 0) start = 0;
        if (start > TT) start = TT;
        int end = (endl > TT) ? TT : (int)endl;
        if (end < start) end = start;
        sh_bounds[0] = start;
        sh_bounds[1] = end;
        // init mbarriers (single arriver: the expect_tx arrive)
        uint32_t b0 = smem_u32(&mbar[0]);
        uint32_t b1 = smem_u32(&mbar[1]);
        asm volatile("mbarrier.init.shared.b64 [%0], 1;" :: "r"(b0) : "memory");
        asm volatile("mbarrier.init.shared.b64 [%0], 1;" :: "r"(b1) : "memory");
        asm volatile("fence.proxy.async.shared::cta;" ::: "memory");
    }
    __syncthreads();
    const int start = sh_bounds[0];
    const int end   = sh_bounds[1];
    const int len   = end - start;
    const int nchunks = (len + CHUNK - 1) / CHUNK;

    const float4* base = reinterpret_cast<const float4*>(wv + (size_t)b * TT * DD);
    const char* src_base = reinterpret_cast<const char*>(wv + (size_t)b * TT * DD
                                                            + (size_t)start * DD);

    // Producer: issue chunk i into stage i&1 (tid 0 only).
    auto issue = [&](int i) {
        int t0 = i * CHUNK;
        int rows = len - t0;
        if (rows > CHUNK) rows = CHUNK;
        uint32_t bytes = (uint32_t)rows * DD * 4u;
        uint32_t dst = smem_u32(&buf[i & 1][0]);
        uint32_t bar = smem_u32(&mbar[i & 1]);
        asm volatile("mbarrier.arrive.expect_tx.shared.b64 _, [%0], %1;"
                     :: "r"(bar), "r"(bytes) : "memory");
        asm volatile(
            "cp.async.bulk.shared::cluster.global.mbarrier::complete_tx::bytes "
            "[%0], [%1], %2, [%3];"
            :: "r"(dst), "l"(src_base + (size_t)t0 * DD * 4), "r"(bytes), "r"(bar)
            : "memory");
    };
    if (tid == 0) {
        if (nchunks > 0) issue(0);
        if (nchunks > 1) issue(1);
    }

    // Rep gather overlaps with the pipeline (its row is inside this span here).
    int rid = rep_ids[b * SS + s];
    if (rid < 0) rid = 0;
    if (rid >= TT) rid = TT - 1;
    float4 r = __ldg(base + (size_t)rid * D4 + tid);

    float sx = 0.f, sy = 0.f, sz = 0.f, sw = 0.f;
    float cx = 0.f, cy = 0.f, cz = 0.f, cw = 0.f;

    for (int i = 0; i < nchunks; i++) {
        const int stage = i & 1;
        const uint32_t parity = (uint32_t)((i >> 1) & 1);
        mbar_wait(smem_u32(&mbar[stage]), parity);

        int rows = len - i * CHUNK;
        if (rows > CHUNK) rows = CHUNK;
        const float4* bp = reinterpret_cast<const float4*>(&buf[stage][0]);
        #pragma unroll
        for (int rr = 0; rr < CHUNK; rr++) {
            if (rr < rows) {
                float4 v = bp[rr * D4 + tid];
                sx += v.x; sy += v.y; sz += v.z; sw += v.w;
                cx += (v.x != 0.f) ? 1.f : 0.f;
                cy += (v.y != 0.f) ? 1.f : 0.f;
                cz += (v.z != 0.f) ? 1.f : 0.f;
                cw += (v.w != 0.f) ? 1.f : 0.f;
            }
        }
        __syncthreads();   // all threads done reading this stage
        if (tid == 0 && i + 2 < nchunks) issue(i + 2);
    }

    // Whole-segment emptiness check (seg_cnt.sum(-1) == 0), warp-shuffle reduce.
    float tot = cx + cy + cz + cw;
    #pragma unroll
    for (int off = 16; off > 0; off >>= 1)
        tot += __shfl_xor_sync(0xffffffffu, tot, off);
    if (lane == 0) sh_warp[wid] = tot;
    __syncthreads();
    float block_tot = sh_warp[0] + sh_warp[1] + sh_warp[2]
                    + sh_warp[3] + sh_warp[4] + sh_warp[5];
    const bool empty = (block_tot == 0.f);

    const float lm = (len_mask[b * SS + s] != 0) ? 1.f : 0.f;
    const float rm = (rep_mask[b * SS + s] != 0) ? 1.f : 0.f;

    float4 o;
    if (empty) {
        // fallback to word_vectors[0, 0, :]
        float4 w0 = __ldg(reinterpret_cast<const float4*>(wv) + tid);
        o.x = w0.x * lm; o.y = w0.y * lm; o.z = w0.z * lm; o.w = w0.w * lm;
    } else {
        float dx = (cx == 0.f) ? 1.f : cx;
        float dy = (cy == 0.f) ? 1.f : cy;
        float dz = (cz == 0.f) ? 1.f : cz;
        float dw = (cw == 0.f) ? 1.f : cw;
        o.x = (sx / dx) * lm;
        o.y = (sy / dy) * lm;
        o.z = (sz / dz) * lm;
        o.w = (sw / dw) * lm;
    }
    float4* out4 = reinterpret_cast<float4*>(out);
    // mean_vec -> out[b, S + s, :]
    __stcs(&out4[((size_t)b * 2 * SS + SS + s) * D4 + tid], o);
    // rep_vec -> out[b, s, :]
    r.x *= rm; r.y *= rm; r.z *= rm; r.w *= rm;
    __stcs(&out4[((size_t)b * 2 * SS + s) * D4 + tid], r);

    // output mask tail (flattened tuple): out_tail[b, c] with c in [0, 2S)
    if (write_mask_tail) {
        float* out_tail = out + OUT_VEC;
        if (tid == 0) out_tail[b * 2 * SS + s]      = rm;   // rep mask half
        if (tid == 1) out_tail[b * 2 * SS + SS + s] = lm;   // len mask half
    }
}

extern "C" void kernel_launch(void* const* d_in, const int* in_sizes, int n_in,
                              void* d_out, int out_size)
{
    const float* wv       = (const float*)d_in[0];
    const int*   rep_ids  = (const int*)d_in[1];
    const int*   rep_mask = (const int*)d_in[2];
    const int*   lens     = (const int*)d_in[3];
    const int*   len_mask = (const int*)d_in[4];
    float* out = (float*)d_out;

    int write_mask_tail = ((size_t)out_size > OUT_VEC) ? 1 : 0;
    pooling_kernel<<<BB * SS, 192>>>(wv, rep_ids, rep_mask, lens, len_mask, out,
                                     write_mask_tail);
}